// round 3
// baseline (speedup 1.0000x reference)
#include <cuda_runtime.h>
#include <math.h>

// Problem shape (fixed by setup_inputs): B=256 rows, C=2048 features,
// groups of K=4 identical targets. Output = loss of the LAST center only.
#define BDIM 256
#define CDIM 2048
#define NSLICE 8            // split-K slices for the GEMM
#define KC (CDIM / NSLICE)  // 256 k's per slice
#define KB 32               // k's per smem stage
#define NSTG (KC / KB)      // 8 stages per slice
#define TILE 64             // output tile side
#define LDSR 34             // smem row stride (floats): pad 32 -> 34, conflict-free LDS.64

// Scratch (no allocations allowed): normalized vectors + split-K partial Gram.
__device__ float d_V[BDIM * CDIM];             // 2 MB
__device__ float d_Gp[NSLICE][BDIM * BDIM];    // 8 * 256 KB = 2 MB

// Packed fp32x2 FMA (sm_10x): doubles fp32 FMA throughput vs scalar FFMA.
__device__ __forceinline__ void ffma2(unsigned long long& d,
                                      unsigned long long a,
                                      unsigned long long b) {
    asm("fma.rn.f32x2 %0, %1, %2, %0;" : "+l"(d) : "l"(a), "l"(b));
}

// ---------------------------------------------------------------------------
// Kernel 1: center of the last target group + row-normalize (inputs - c).
// One block per row; 256 threads, each owns 8 columns (tid + 256*q).
// Also zeroes the output accumulator (d_out is poisoned by the harness).
// ---------------------------------------------------------------------------
__global__ void __launch_bounds__(256) prep_kernel(const float* __restrict__ x,
                                                   const int* __restrict__ tg,
                                                   float* __restrict__ out) {
    __shared__ int mlist[BDIM];
    __shared__ int mcount;
    __shared__ float ws[8];

    const int tid = threadIdx.x;
    const int row = blockIdx.x;

    if (tid == 0) mcount = 0;
    __syncthreads();

    const int t_last = tg[BDIM - 4];  // targets[::4][-1]
    if (tg[tid] == t_last) {
        int p = atomicAdd(&mcount, 1);
        mlist[p] = tid;
    }
    __syncthreads();
    const int cnt = mcount;

    float acc[8];
#pragma unroll
    for (int q = 0; q < 8; q++) acc[q] = 0.f;
    for (int m = 0; m < cnt; m++) {
        const int r = mlist[m];
#pragma unroll
        for (int q = 0; q < 8; q++) acc[q] += x[r * CDIM + tid + 256 * q];
    }
    const float inv = 1.f / (float)cnt;

    float v[8];
    float ss = 0.f;
#pragma unroll
    for (int q = 0; q < 8; q++) {
        float d = x[row * CDIM + tid + 256 * q] - acc[q] * inv;
        v[q] = d;
        ss += d * d;
    }
#pragma unroll
    for (int o = 16; o; o >>= 1) ss += __shfl_xor_sync(0xffffffffu, ss, o);
    if ((tid & 31) == 0) ws[tid >> 5] = ss;
    __syncthreads();
    float tot = 0.f;
#pragma unroll
    for (int i = 0; i < 8; i++) tot += ws[i];

    const float rn = 1.f / fmaxf(sqrtf(tot), 1e-12f);
#pragma unroll
    for (int q = 0; q < 8; q++) d_V[row * CDIM + tid + 256 * q] = v[q] * rn;

    if (row == 0 && tid == 0) *out = 0.f;
}

// ---------------------------------------------------------------------------
// Kernel 2: split-K Gram GEMM  G = V V^T.
// Grid (4, 4, NSLICE): 64x64 tile per block, K-slice of 256, no atomics —
// each slice writes its own partial buffer. Double-buffered smem with
// register prefetch; fp32x2 k-parity accumulators (acc.x = even-k, .y = odd-k).
// Thread map: tx = tid&15 (j, strided x4), ty = tid>>4 (i, strided x4).
// ---------------------------------------------------------------------------
__global__ void __launch_bounds__(256) gemm_kernel() {
    __shared__ __align__(16) float As[2][TILE * LDSR];
    __shared__ __align__(16) float Bs[2][TILE * LDSR];

    const int tid = threadIdx.x;
    const int tx = tid & 15;
    const int ty = tid >> 4;
    const int jt = blockIdx.x;
    const int it = blockIdx.y;
    const int s  = blockIdx.z;
    const int k0 = s * KC;

    const int lr = tid >> 4;  // row-within-16 for the loader
    const int lk = tid & 15;  // k-pair index for the loader

    float2 pre[8];
    unsigned long long acc[16];
#pragma unroll
    for (int i = 0; i < 16; i++) acc[i] = 0ull;

    // Stage loaders: 64x32 floats per tile = 1024 float2 = 4 per thread.
    auto gload = [&](int st) {
        const int kb = k0 + st * KB + 2 * lk;
#pragma unroll
        for (int q = 0; q < 4; q++) {
            pre[q]     = *(const float2*)(d_V + (it * TILE + lr + 16 * q) * CDIM + kb);
            pre[4 + q] = *(const float2*)(d_V + (jt * TILE + lr + 16 * q) * CDIM + kb);
        }
    };
    auto sstore = [&](int b) {
#pragma unroll
        for (int q = 0; q < 4; q++) {
            *(float2*)(&As[b][(lr + 16 * q) * LDSR + 2 * lk]) = pre[q];
            *(float2*)(&Bs[b][(lr + 16 * q) * LDSR + 2 * lk]) = pre[4 + q];
        }
    };

    gload(0);
    sstore(0);
    __syncthreads();

    for (int st = 0; st < NSTG; st++) {
        if (st + 1 < NSTG) gload(st + 1);  // prefetch next stage into regs

        const float* Ap = As[st & 1];
        const float* Bp = Bs[st & 1];
#pragma unroll
        for (int kp = 0; kp < KB / 2; kp++) {
            unsigned long long af[4], bf[4];
#pragma unroll
            for (int ii = 0; ii < 4; ii++)
                af[ii] = *(const unsigned long long*)(Ap + (ty + 16 * ii) * LDSR + 2 * kp);
#pragma unroll
            for (int jj = 0; jj < 4; jj++)
                bf[jj] = *(const unsigned long long*)(Bp + (tx + 16 * jj) * LDSR + 2 * kp);
#pragma unroll
            for (int ii = 0; ii < 4; ii++)
#pragma unroll
                for (int jj = 0; jj < 4; jj++)
                    ffma2(acc[ii * 4 + jj], af[ii], bf[jj]);
        }

        if (st + 1 < NSTG) sstore((st + 1) & 1);
        __syncthreads();
    }

    float* __restrict__ G = d_Gp[s];
#pragma unroll
    for (int ii = 0; ii < 4; ii++)
#pragma unroll
        for (int jj = 0; jj < 4; jj++) {
            const unsigned long long u = acc[ii * 4 + jj];
            const float r = __uint_as_float((unsigned)u) +
                            __uint_as_float((unsigned)(u >> 32));
            G[(it * TILE + ty + 16 * ii) * BDIM + jt * TILE + tx + 16 * jj] = r;
        }
}

// ---------------------------------------------------------------------------
// Kernel 3: per-row masked min/max over the summed K-slices + final sum.
// One warp per row (32 blocks x 8 warps = 256 warps).
// pos = min over same-target j (includes the diagonal, == 1);
// neg = max over different-target j of relu(G); result += exp(neg - pos)/448.
// ---------------------------------------------------------------------------
__global__ void __launch_bounds__(256) reduce_kernel(const int* __restrict__ tg,
                                                     float* __restrict__ out) {
    const int gt = blockIdx.x * 256 + threadIdx.x;
    const int row = gt >> 5;
    const int lane = gt & 31;
    const int trow = tg[row];
    const float INF = __int_as_float(0x7f800000);

    float pos = INF;
    float neg = 0.f;
#pragma unroll
    for (int jj = 0; jj < 8; jj++) {
        const int j = lane + 32 * jj;
        float g = 0.f;
#pragma unroll
        for (int s = 0; s < NSLICE; s++) g += d_Gp[s][row * BDIM + j];
        const bool same = (tg[j] == trow);
        pos = fminf(pos, same ? g : INF);
        neg = fmaxf(neg, same ? 0.f : fmaxf(g, 0.f));
    }
#pragma unroll
    for (int o = 16; o; o >>= 1) {
        pos = fminf(pos, __shfl_xor_sync(0xffffffffu, pos, o));
        neg = fmaxf(neg, __shfl_xor_sync(0xffffffffu, neg, o));
    }
    if (lane == 0) atomicAdd(out, expf(neg - pos) * (1.f / 448.f));
}

// ---------------------------------------------------------------------------
extern "C" void kernel_launch(void* const* d_in, const int* in_sizes, int n_in,
                              void* d_out, int out_size) {
    const float* x  = (const float*)d_in[0];   // inputs  [256, 2048] fp32
    const int*   tg = (const int*)d_in[1];     // targets [256] int32
    // d_in[2] (subs) is unused by the reference math.
    float* out = (float*)d_out;                // scalar fp32

    prep_kernel<<<BDIM, 256>>>(x, tg, out);
    gemm_kernel<<<dim3(BDIM / TILE, BDIM / TILE, NSLICE), 256>>>();
    reduce_kernel<<<BDIM / 8, 256>>>(tg, out);
}

// round 4
// speedup vs baseline: 1.2552x; 1.2552x over previous
#include <cuda_runtime.h>
#include <math.h>

// Problem shape (fixed): B=256 rows, C=2048 features, target groups of 4.
// Output = loss of the LAST center only (reference returns losses[-1]).
#define BDIM 256
#define CDIM 2048
#define KB 32                 // k's per smem stage
#define TOTSTG (CDIM / KB)    // 64 stages total
#define NSLICE 14             // uneven split-K slices (4-5 stages each)
#define TILE 64               // output tile side
#define LDSR 34               // smem row stride (floats): conflict-free LDS.64

// Scratch: normalized vectors + single Gram buffer (split-K merged by REDG).
__device__ float d_V[BDIM * CDIM];       // 2 MB
__device__ float d_G[BDIM * BDIM];       // 256 KB

// Upper-triangle 64x64 tile pairs (it <= jt), 10 of 16.
__device__ const int PIT[10] = {0, 0, 0, 0, 1, 1, 1, 2, 2, 3};
__device__ const int PJT[10] = {0, 1, 2, 3, 1, 2, 3, 2, 3, 3};

// Packed fp32x2 FMA (sm_10x): 2 FMA per issue slot on the fma pipe.
__device__ __forceinline__ void ffma2(unsigned long long& d,
                                      unsigned long long a,
                                      unsigned long long b) {
    asm("fma.rn.f32x2 %0, %1, %2, %0;" : "+l"(d) : "l"(a), "l"(b));
}

// ---------------------------------------------------------------------------
// Kernel 1: center of the last group + row-normalize (inputs - c), float4.
// 128 blocks x 512 threads = one wave; each block handles 2 rows.
// Also zeroes d_G (exactly 65536 threads) and the scalar output.
// ---------------------------------------------------------------------------
__global__ void __launch_bounds__(512) prep_kernel(const float4* __restrict__ x4,
                                                   const int* __restrict__ tg,
                                                   float* __restrict__ out) {
    __shared__ int mlist[BDIM];
    __shared__ int mcount;
    __shared__ float ws[2][8];

    const int tid = threadIdx.x;
    const int half = tid >> 8;       // which of the 2 rows
    const int h = tid & 255;         // lane within the row's 256 workers
    const int row = blockIdx.x * 2 + half;

    if (tid == 0) mcount = 0;
    __syncthreads();
    if (tid < BDIM) {
        if (tg[tid] == tg[BDIM - 4]) {     // targets[::4][-1]
            int p = atomicAdd(&mcount, 1);
            mlist[p] = tid;
        }
    }
    __syncthreads();
    const int cnt = mcount;

    // Mean of the matching rows (2 float4 per thread, MLP across iterations).
    float4 a0 = make_float4(0.f, 0.f, 0.f, 0.f);
    float4 a1 = a0;
#pragma unroll 4
    for (int m = 0; m < cnt; m++) {
        const float4* r = x4 + mlist[m] * (CDIM / 4);
        float4 u0 = r[h], u1 = r[h + 256];
        a0.x += u0.x; a0.y += u0.y; a0.z += u0.z; a0.w += u0.w;
        a1.x += u1.x; a1.y += u1.y; a1.z += u1.z; a1.w += u1.w;
    }
    const float inv = 1.f / (float)cnt;

    const float4* xr = x4 + row * (CDIM / 4);
    float4 u0 = xr[h], u1 = xr[h + 256];
    float4 v0 = make_float4(u0.x - a0.x * inv, u0.y - a0.y * inv,
                            u0.z - a0.z * inv, u0.w - a0.w * inv);
    float4 v1 = make_float4(u1.x - a1.x * inv, u1.y - a1.y * inv,
                            u1.z - a1.z * inv, u1.w - a1.w * inv);

    float ss = v0.x * v0.x + v0.y * v0.y + v0.z * v0.z + v0.w * v0.w +
               v1.x * v1.x + v1.y * v1.y + v1.z * v1.z + v1.w * v1.w;
#pragma unroll
    for (int o = 16; o; o >>= 1) ss += __shfl_xor_sync(0xffffffffu, ss, o);
    if ((h & 31) == 0) ws[half][h >> 5] = ss;
    __syncthreads();
    float tot = 0.f;
#pragma unroll
    for (int i = 0; i < 8; i++) tot += ws[half][i];

    const float rn = 1.f / fmaxf(sqrtf(tot), 1e-12f);
    float4* V4 = (float4*)d_V + row * (CDIM / 4);
    V4[h]       = make_float4(v0.x * rn, v0.y * rn, v0.z * rn, v0.w * rn);
    V4[h + 256] = make_float4(v1.x * rn, v1.y * rn, v1.z * rn, v1.w * rn);

    // Zero the Gram accumulator (128*512 == 65536 == BDIM*BDIM).
    d_G[blockIdx.x * 512 + tid] = 0.f;
    if (blockIdx.x == 0 && tid == 0) *out = 0.f;
}

// ---------------------------------------------------------------------------
// Kernel 2: symmetric split-K Gram GEMM, G += V V^T (upper-triangle tiles).
// Grid (10, 14): 10 tile pairs x 14 uneven K-slices (stages [z*64/14,(z+1)*64/14)).
// Double-buffered smem, register prefetch, fp32x2 k-parity accumulators.
// Epilogue: REDG.F32 into d_G; off-diagonal tiles also write the mirror.
// ---------------------------------------------------------------------------
__global__ void __launch_bounds__(256) gemm_kernel() {
    __shared__ __align__(16) float As[2][TILE * LDSR];
    __shared__ __align__(16) float Bs[2][TILE * LDSR];

    const int tid = threadIdx.x;
    const int tx = tid & 15;
    const int ty = tid >> 4;
    const int it = PIT[blockIdx.x];
    const int jt = PJT[blockIdx.x];
    const int s0 = (blockIdx.y * TOTSTG) / NSLICE;
    const int s1 = ((blockIdx.y + 1) * TOTSTG) / NSLICE;

    const int lr = tid >> 4;  // loader row-within-16
    const int lk = tid & 15;  // loader k-pair index

    float2 pre[8];
    unsigned long long acc[16];
#pragma unroll
    for (int i = 0; i < 16; i++) acc[i] = 0ull;

    auto gload = [&](int st) {
        const int kb = st * KB + 2 * lk;
#pragma unroll
        for (int q = 0; q < 4; q++) {
            pre[q]     = *(const float2*)(d_V + (it * TILE + lr + 16 * q) * CDIM + kb);
            pre[4 + q] = *(const float2*)(d_V + (jt * TILE + lr + 16 * q) * CDIM + kb);
        }
    };
    auto sstore = [&](int b) {
#pragma unroll
        for (int q = 0; q < 4; q++) {
            *(float2*)(&As[b][(lr + 16 * q) * LDSR + 2 * lk]) = pre[q];
            *(float2*)(&Bs[b][(lr + 16 * q) * LDSR + 2 * lk]) = pre[4 + q];
        }
    };

    gload(s0);
    sstore(0);
    __syncthreads();

    for (int st = s0; st < s1; st++) {
        const int b = (st - s0) & 1;
        if (st + 1 < s1) gload(st + 1);  // prefetch next stage into regs

        const float* Ap = As[b];
        const float* Bp = Bs[b];
#pragma unroll
        for (int kp = 0; kp < KB / 2; kp++) {
            unsigned long long af[4], bf[4];
#pragma unroll
            for (int ii = 0; ii < 4; ii++)
                af[ii] = *(const unsigned long long*)(Ap + (ty + 16 * ii) * LDSR + 2 * kp);
#pragma unroll
            for (int jj = 0; jj < 4; jj++)
                bf[jj] = *(const unsigned long long*)(Bp + (tx + 16 * jj) * LDSR + 2 * kp);
#pragma unroll
            for (int ii = 0; ii < 4; ii++)
#pragma unroll
                for (int jj = 0; jj < 4; jj++)
                    ffma2(acc[ii * 4 + jj], af[ii], bf[jj]);
        }

        if (st + 1 < s1) sstore(b ^ 1);
        __syncthreads();
    }

#pragma unroll
    for (int ii = 0; ii < 4; ii++)
#pragma unroll
        for (int jj = 0; jj < 4; jj++) {
            const unsigned long long u = acc[ii * 4 + jj];
            const float r = __uint_as_float((unsigned)u) +
                            __uint_as_float((unsigned)(u >> 32));
            const int gi = it * TILE + ty + 16 * ii;
            const int gj = jt * TILE + tx + 16 * jj;
            atomicAdd(&d_G[gi * BDIM + gj], r);          // REDG.F32 (no return)
            if (it != jt) atomicAdd(&d_G[gj * BDIM + gi], r);
        }
}

// ---------------------------------------------------------------------------
// Kernel 3: per-row masked min/max over G + final sum. One warp per row.
// ---------------------------------------------------------------------------
__global__ void __launch_bounds__(256) reduce_kernel(const int* __restrict__ tg,
                                                     float* __restrict__ out) {
    const int gt = blockIdx.x * 256 + threadIdx.x;
    const int row = gt >> 5;
    const int lane = gt & 31;
    const int trow = tg[row];
    const float INF = __int_as_float(0x7f800000);

    float pos = INF;
    float neg = 0.f;
#pragma unroll
    for (int jj = 0; jj < 8; jj++) {
        const int j = lane + 32 * jj;
        const float g = d_G[row * BDIM + j];
        const bool same = (tg[j] == trow);
        pos = fminf(pos, same ? g : INF);
        neg = fmaxf(neg, same ? 0.f : fmaxf(g, 0.f));
    }
#pragma unroll
    for (int o = 16; o; o >>= 1) {
        pos = fminf(pos, __shfl_xor_sync(0xffffffffu, pos, o));
        neg = fmaxf(neg, __shfl_xor_sync(0xffffffffu, neg, o));
    }
    if (lane == 0) atomicAdd(out, expf(neg - pos) * (1.f / 448.f));
}

// ---------------------------------------------------------------------------
extern "C" void kernel_launch(void* const* d_in, const int* in_sizes, int n_in,
                              void* d_out, int out_size) {
    const float4* x4 = (const float4*)d_in[0];  // inputs  [256, 2048] fp32
    const int*    tg = (const int*)d_in[1];     // targets [256] int32
    // d_in[2] (subs) is unused by the reference math.
    float* out = (float*)d_out;                 // scalar fp32

    prep_kernel<<<BDIM / 2, 512>>>(x4, tg, out);
    gemm_kernel<<<dim3(10, NSLICE), 256>>>();
    reduce_kernel<<<BDIM / 8, 256>>>(tg, out);
}